// round 11
// baseline (speedup 1.0000x reference)
#include <cuda_runtime.h>
#include <cuda_fp16.h>
#include <stdint.h>

typedef unsigned long long ull;
typedef unsigned int uint;

// ---------------------------------------------------------------------------
// Problem constants
// ---------------------------------------------------------------------------
#define N_KERNELS 10000
#define IN_CH 3
#define T_LEN 1024
#define BATCH 64
#define MAXK 11
#define W_STRIDE (IN_CH * MAXK)     // 33
#define NGROUPS 15
#define NDIL 5
#define CHUNK 32                    // kernels per chunk (2 m-tiles of 16)
#define MAXCH 352
#define SCW 4                       // chunks per superchunk (same dilation)
#define MAXSC 96
#define OUT_STRIDE (2 * N_KERNELS)
#define PADL 80
#define XPE 1216                    // PADL + 1024 + 96 (max right reach) + pad
#define XPAIR (IN_CH * XPE)         // 3648 u32 per (batch, dil)
#define NKMAX 3                     // k16 chunks: k=7:2, k=9:2, k=11:3

__constant__ int c_dils[NDIL] = {1, 2, 4, 8, 16};

// ---------------------------------------------------------------------------
// Device-global scratch
// ---------------------------------------------------------------------------
__device__ uint8_t g_kidx[N_KERNELS];
__device__ uint8_t g_didx[N_KERNELS];
__device__ uint8_t g_garr[N_KERNELS];
__device__ int     g_sorted[N_KERNELS];
__device__ int     g_nch;
__device__ int4    g_chunks[MAXCH];          // {start, count, k, didx}
__device__ int     g_nsc;
__device__ int4    g_sc[MAXSC];              // {ci0, nchunks, didx, 0}
__device__ int     g_rng_bad;                // static-init 0
__device__ __align__(16) uint4 g_wfrag[MAXCH * 2 * NKMAX * 32]; // A fragments
__device__ float   g_biasT[MAXCH * CHUNK];
__device__ __align__(16) uint g_xpair[BATCH * NDIL * XPAIR];    // {xh[i],xh[i+d]}

// ---------------------------------------------------------------------------
// NumPy default_rng(0): SeedSequence -> PCG64 (XSL-RR) -> Lemire  (validated)
// ---------------------------------------------------------------------------
#define PCG_MH 2549297995355413924ull
#define PCG_ML 4865540595714422341ull

struct Pcg { ull shi, slo, ihi, ilo; int has32; uint buf; };

__device__ __forceinline__ void mul128(ull alo, ull ahi, ull blo, ull bhi,
                                       ull &rlo, ull &rhi) {
    rlo = alo * blo;
    rhi = __umul64hi(alo, blo) + alo * bhi + ahi * blo;
}
__device__ __forceinline__ void add128(ull &alo, ull &ahi, ull blo, ull bhi) {
    ull t = alo + blo;
    ahi = ahi + bhi + (t < alo ? 1ull : 0ull);
    alo = t;
}
__device__ __forceinline__ void pcg_step(Pcg &p) {
    ull nlo, nhi;
    mul128(p.slo, p.shi, PCG_ML, PCG_MH, nlo, nhi);
    add128(nlo, nhi, p.ilo, p.ihi);
    p.slo = nlo; p.shi = nhi;
}
__device__ __forceinline__ ull pcg_out(ull slo, ull shi) {
    uint rot = (uint)(shi >> 58);
    ull x = shi ^ slo;
    return (x >> rot) | (x << ((64u - rot) & 63u));
}
__device__ __forceinline__ uint pcg_next32(Pcg &p) {
    if (p.has32) { p.has32 = 0; return p.buf; }
    pcg_step(p);
    ull v = pcg_out(p.slo, p.shi);
    p.has32 = 1;
    p.buf = (uint)(v >> 32);
    return (uint)v;
}
__device__ __forceinline__ uint lemire32(Pcg &p, uint excl) {
    ull m = (ull)pcg_next32(p) * (ull)excl;
    uint leftover = (uint)m;
    if (leftover < excl) {
        uint thr = (uint)(0u - excl) % excl;
        while (leftover < thr) {
            m = (ull)pcg_next32(p) * (ull)excl;
            leftover = (uint)m;
        }
    }
    return (uint)(m >> 32);
}
__device__ __forceinline__ uint hashmix32(uint v, uint *hc) {
    v ^= *hc; *hc *= 0x931e8875u; v *= *hc; v ^= v >> 16; return v;
}
__device__ __forceinline__ uint mix32(uint x, uint y) {
    uint r = x * 0xca01f9ddu - y * 0x4973f715u;
    r ^= r >> 16; return r;
}
__device__ void pcg_seed0(Pcg &p) {
    uint pool[4];
    uint hc = 0x43b0d7e5u;
    for (int i = 0; i < 4; i++) pool[i] = hashmix32(0u, &hc);
    for (int s = 0; s < 4; s++)
        for (int d = 0; d < 4; d++)
            if (s != d) pool[d] = mix32(pool[d], hashmix32(pool[s], &hc));
    uint hb = 0x8b51f9ddu;
    uint w32[8];
    for (int i = 0; i < 8; i++) {
        uint v = pool[i & 3];
        v ^= hb; hb *= 0x58f38dedu; v *= hb; v ^= v >> 16;
        w32[i] = v;
    }
    ull s0 = (ull)w32[0] | ((ull)w32[1] << 32);
    ull s1 = (ull)w32[2] | ((ull)w32[3] << 32);
    ull s2 = (ull)w32[4] | ((ull)w32[5] << 32);
    ull s3 = (ull)w32[6] | ((ull)w32[7] << 32);
    p.shi = 0; p.slo = 0;
    p.ihi = (s2 << 1) | (s3 >> 63);
    p.ilo = (s3 << 1) | 1ull;
    p.has32 = 0; p.buf = 0;
    pcg_step(p);
    add128(p.slo, p.shi, s1, s0);
    pcg_step(p);
}

// Parallel RNG via LCG jump-ahead; flags the (p~5e-6) Lemire-rejection case.
__global__ void rng_par() {
    int n = blockIdx.x * blockDim.x + threadIdx.x;
    if (n >= N_KERNELS) return;
    Pcg p;
    pcg_seed0(p);
    ull delta = (ull)(n + 1);
    ull am_lo = 1, am_hi = 0, ap_lo = 0, ap_hi = 0;
    ull cm_lo = PCG_ML, cm_hi = PCG_MH;
    ull cp_lo = p.ilo, cp_hi = p.ihi;
    while (delta) {
        if (delta & 1) {
            ull tlo, thi;
            mul128(am_lo, am_hi, cm_lo, cm_hi, tlo, thi);
            am_lo = tlo; am_hi = thi;
            mul128(ap_lo, ap_hi, cm_lo, cm_hi, tlo, thi);
            add128(tlo, thi, cp_lo, cp_hi);
            ap_lo = tlo; ap_hi = thi;
        }
        ull e_lo = cm_lo + 1;
        ull e_hi = cm_hi + (e_lo == 0 ? 1ull : 0ull);
        ull tlo, thi;
        mul128(e_lo, e_hi, cp_lo, cp_hi, tlo, thi);
        cp_lo = tlo; cp_hi = thi;
        mul128(cm_lo, cm_hi, cm_lo, cm_hi, tlo, thi);
        cm_lo = tlo; cm_hi = thi;
        delta >>= 1;
    }
    ull slo, shi;
    mul128(p.slo, p.shi, am_lo, am_hi, slo, shi);
    add128(slo, shi, ap_lo, ap_hi);
    ull out = pcg_out(slo, shi);
    uint lo = (uint)out;
    uint hi = (uint)(out >> 32);
    if (lo == 0u || hi == 0u) atomicOr(&g_rng_bad, 1);
    if (n < N_KERNELS / 2) {
        int j = 2 * n;
        g_kidx[j]     = (uint8_t)(((ull)lo * 3ull) >> 32);
        g_kidx[j + 1] = (uint8_t)(((ull)hi * 3ull) >> 32);
    } else {
        int j = 2 * n - N_KERNELS;
        g_didx[j]     = (uint8_t)(((ull)lo * 5ull) >> 32);
        g_didx[j + 1] = (uint8_t)(((ull)hi * 5ull) >> 32);
    }
}

// ---------------------------------------------------------------------------
// Fused: sequential RNG fallback (rare) + grouping + chunk/superchunk tables.
// Group id is DILATION-MAJOR (g = didx*3 + kidx) so same-dilation chunks are
// contiguous and superchunks can share one x pair-image.
// ---------------------------------------------------------------------------
__global__ void __launch_bounds__(1024)
group_fused() {
    __shared__ int cnt[NGROUPS];
    __shared__ int off[NGROUPS];
    int tid = threadIdx.x;

    if (tid == 0 && g_rng_bad) {       // exact sequential fallback
        Pcg p;
        pcg_seed0(p);
        for (int i = 0; i < N_KERNELS; i++) g_kidx[i] = (uint8_t)lemire32(p, 3u);
        for (int i = 0; i < N_KERNELS; i++) g_didx[i] = (uint8_t)lemire32(p, 5u);
        g_rng_bad = 0;
    }
    if (tid < NGROUPS) cnt[tid] = 0;
    __syncthreads();

    for (int i = tid; i < N_KERNELS; i += 1024) {
        int g = (int)g_didx[i] * 3 + (int)g_kidx[i];
        g_garr[i] = (uint8_t)g;
        atomicAdd(&cnt[g], 1);
    }
    __syncthreads();

    if (tid == 0) {
        int o = 0, nch = 0;
        for (int g = 0; g < NGROUPS; g++) {
            int ks   = 7 + 2 * (g % 3);
            int didx = g / 3;
            int n    = cnt[g];
            off[g] = o;
            for (int s = 0; s < n; s += CHUNK) {
                int4 ch;
                ch.x = o + s;
                ch.y = (n - s < CHUNK) ? (n - s) : CHUNK;
                ch.z = ks;
                ch.w = didx;
                g_chunks[nch++] = ch;
            }
            o += n;
        }
        g_nch = nch;
        // superchunks: up to SCW consecutive chunks sharing a dilation
        int nsc = 0, i = 0;
        while (i < nch) {
            int d = g_chunks[i].w;
            int n = 0;
            while (n < SCW && i + n < nch && g_chunks[i + n].w == d) n++;
            int4 s;
            s.x = i; s.y = n; s.z = d; s.w = 0;
            g_sc[nsc++] = s;
            i += n;
        }
        g_nsc = nsc;
    }
    __syncthreads();

    for (int i = tid; i < N_KERNELS; i += 1024) {
        int p = atomicAdd(&off[g_garr[i]], 1);
        g_sorted[p] = i;
    }
}

// ---------------------------------------------------------------------------
// A-fragment image: fp16 weights, tap-pair K layout.
// Per channel c: S = k+1 slots (even); slot j<k holds w[c][j], slot k = 0.
// ---------------------------------------------------------------------------
__device__ __forceinline__ unsigned short whalf(const float* __restrict__ weights,
                                                const int* __restrict__ sorted,
                                                int start, int count, int k,
                                                int row, int slot) {
    int S = k + 1;
    float v = 0.0f;
    if (row < count && slot < 3 * S) {
        int c = slot / S;
        int j = slot - c * S;
        if (j < k)
            v = weights[sorted[start + row] * W_STRIDE + c * MAXK + j];
    }
    __half h = __float2half(v);
    unsigned short u;
    memcpy(&u, &h, 2);
    return u;
}

__global__ void wimg_kernel(const float* __restrict__ weights,
                            const float* __restrict__ biases) {
    int ci = blockIdx.x;
    if (ci >= g_nch) return;
    int4 ch = g_chunks[ci];
    int start = ch.x, count = ch.y, k = ch.z;

    for (int idx = threadIdx.x; idx < 2 * NKMAX * 32; idx += blockDim.x) {
        int mt   = idx / (NKMAX * 32);
        int rem  = idx - mt * (NKMAX * 32);
        int kc   = rem / 32;
        int lane = rem & 31;
        int g = lane >> 2;
        int t = lane & 3;
        int r0 = mt * 16 + g;
        int r1 = r0 + 8;
        int k0 = kc * 16 + 2 * t;
        uint4 f;
        f.x = (uint)whalf(weights, g_sorted, start, count, k, r0, k0)
            | ((uint)whalf(weights, g_sorted, start, count, k, r0, k0 + 1) << 16);
        f.y = (uint)whalf(weights, g_sorted, start, count, k, r1, k0)
            | ((uint)whalf(weights, g_sorted, start, count, k, r1, k0 + 1) << 16);
        f.z = (uint)whalf(weights, g_sorted, start, count, k, r0, k0 + 8)
            | ((uint)whalf(weights, g_sorted, start, count, k, r0, k0 + 9) << 16);
        f.w = (uint)whalf(weights, g_sorted, start, count, k, r1, k0 + 8)
            | ((uint)whalf(weights, g_sorted, start, count, k, r1, k0 + 9) << 16);
        g_wfrag[(ci * 2 + mt) * (NKMAX * 32) + kc * 32 + lane] = f;
    }
    if (threadIdx.x < CHUNK) {
        float b = 0.0f;
        if (threadIdx.x < count) b = biases[g_sorted[start + threadIdx.x]];
        g_biasT[ci * CHUNK + threadIdx.x] = b;
    }
}

// ---------------------------------------------------------------------------
// Pair image per (batch, dilation): P[c][i] = {fp16(x[i-PADL]), fp16(x[i-PADL+d])}
// ---------------------------------------------------------------------------
__global__ void xpair_kernel(const float* __restrict__ x) {
    int d_idx = blockIdx.x;
    int b = blockIdx.y;
    int dil = c_dils[d_idx];
    uint* dst = g_xpair + (b * NDIL + d_idx) * XPAIR;
    const float* xb = x + b * IN_CH * T_LEN;
    for (int i = threadIdx.x; i < XPAIR; i += blockDim.x) {
        int c = i / XPE;
        int p = i - c * XPE;
        int t1 = p - PADL;
        int t2 = t1 + dil;
        float f1 = ((unsigned)t1 < T_LEN) ? xb[c * T_LEN + t1] : 0.0f;
        float f2 = ((unsigned)t2 < T_LEN) ? xb[c * T_LEN + t2] : 0.0f;
        __half h1 = __float2half(f1);
        __half h2 = __float2half(f2);
        unsigned short u1, u2;
        memcpy(&u1, &h1, 2);
        memcpy(&u2, &h2, 2);
        dst[i] = (uint)u1 | ((uint)u2 << 16);
    }
}

// ---------------------------------------------------------------------------
// Main HMMA kernel (superchunked: one xs image serves up to SCW chunks)
// ---------------------------------------------------------------------------
__device__ __forceinline__ void mma16816h(float c[4], uint4 a, uint b0, uint b1) {
    asm("mma.sync.aligned.m16n8k16.row.col.f32.f16.f16.f32 "
        "{%0,%1,%2,%3}, {%4,%5,%6,%7}, {%8,%9}, {%0,%1,%2,%3};"
        : "+f"(c[0]), "+f"(c[1]), "+f"(c[2]), "+f"(c[3])
        : "r"(a.x), "r"(a.y), "r"(a.z), "r"(a.w), "r"(b0), "r"(b1));
}

// Base u32 index into the pair image for EVEN K slot s (pair base tap).
template <int K>
__device__ __forceinline__ int pslot(int s, int dil) {
    const int S = K + 1;
    const int h = (K - 1) / 2;
    if (s >= 3 * S) return 0;
    int c = s / S;
    int j = s - c * S;
    return c * XPE + PADL + (j - h) * dil;
}

template <int K, int NK>
__device__ __forceinline__ void run_mma(int4 ch, int b, int ci,
                                        const uint* __restrict__ xs,
                                        float (*sredm)[CHUNK], int (*sredc)[CHUNK],
                                        float* __restrict__ out) {
    const int tid  = threadIdx.x;
    const int warp = tid >> 5;
    const int lane = tid & 31;
    const int g = lane >> 2;
    const int t = lane & 3;
    const int dil = 1 << ch.w;
    const int wg = warp * 256 + g;

    // B base indices (u32) per kc for this lane
    uint ix0[NK], ix1[NK];
    #pragma unroll
    for (int kc = 0; kc < NK; kc++) {
        ix0[kc] = (uint)(pslot<K>(kc * 16 + 2 * t, dil) + wg);
        ix1[kc] = (uint)(pslot<K>(kc * 16 + 2 * t + 8, dil) + wg);
    }

    // A fragments (registers for the whole chunk)
    uint4 a0[NK], a1[NK];
    {
        const uint4* wf = g_wfrag + (ci * 2) * (NKMAX * 32);
        #pragma unroll
        for (int kc = 0; kc < NK; kc++) {
            a0[kc] = wf[kc * 32 + lane];
            a1[kc] = wf[NKMAX * 32 + kc * 32 + lane];
        }
    }

    // negated biases for this thread's 4 C rows
    float nb[4];
    nb[0] = -g_biasT[ci * CHUNK + g];
    nb[1] = -g_biasT[ci * CHUNK + g + 8];
    nb[2] = -g_biasT[ci * CHUNK + 16 + g];
    nb[3] = -g_biasT[ci * CHUNK + 24 + g];

    float mx[4] = {-3.4e38f, -3.4e38f, -3.4e38f, -3.4e38f};
    int ct[4] = {0, 0, 0, 0};

    #pragma unroll 8
    for (int nt = 0; nt < 32; nt++) {
        float C0[4] = {0, 0, 0, 0};
        float C1[4] = {0, 0, 0, 0};
        #pragma unroll
        for (int kc = 0; kc < NK; kc++) {
            uint b0 = xs[ix0[kc] + nt * 8];
            uint b1 = xs[ix1[kc] + nt * 8];
            mma16816h(C0, a0[kc], b0, b1);
            mma16816h(C1, a1[kc], b0, b1);
        }
        mx[0] = fmaxf(mx[0], fmaxf(C0[0], C0[1]));
        mx[1] = fmaxf(mx[1], fmaxf(C0[2], C0[3]));
        mx[2] = fmaxf(mx[2], fmaxf(C1[0], C1[1]));
        mx[3] = fmaxf(mx[3], fmaxf(C1[2], C1[3]));
        if (C0[0] > nb[0]) ct[0]++;
        if (C0[1] > nb[0]) ct[0]++;
        if (C0[2] > nb[1]) ct[1]++;
        if (C0[3] > nb[1]) ct[1]++;
        if (C1[0] > nb[2]) ct[2]++;
        if (C1[1] > nb[2]) ct[2]++;
        if (C1[2] > nb[3]) ct[3]++;
        if (C1[3] > nb[3]) ct[3]++;
    }

    // reduce across the 4 threads sharing each row
    #pragma unroll
    for (int o = 1; o <= 2; o <<= 1) {
        #pragma unroll
        for (int i = 0; i < 4; i++) {
            mx[i] = fmaxf(mx[i], __shfl_xor_sync(0xffffffffu, mx[i], o));
            ct[i] += __shfl_xor_sync(0xffffffffu, ct[i], o);
        }
    }
    if (t == 0) {
        sredm[warp][g]      = mx[0];  sredc[warp][g]      = ct[0];
        sredm[warp][g + 8]  = mx[1];  sredc[warp][g + 8]  = ct[1];
        sredm[warp][g + 16] = mx[2];  sredc[warp][g + 16] = ct[2];
        sredm[warp][g + 24] = mx[3];  sredc[warp][g + 24] = ct[3];
    }
    __syncthreads();

    if (tid < CHUNK && tid < ch.y) {
        float m = sredm[0][tid];
        int c2 = sredc[0][tid];
        #pragma unroll
        for (int w = 1; w < 4; w++) {
            m = fmaxf(m, sredm[w][tid]);
            c2 += sredc[w][tid];
        }
        int orig = g_sorted[ch.x + tid];
        float bias = g_biasT[ci * CHUNK + tid];
        float2 o;
        o.x = m + bias;
        o.y = (float)c2 * (1.0f / 1024.0f);
        *(float2*)(out + (size_t)b * OUT_STRIDE + 2 * orig) = o;
    }
}

__global__ void __launch_bounds__(128)
rocket_mma(float* __restrict__ out) {
    int sc = blockIdx.x;
    if (sc >= g_nsc) return;
    int4 s = g_sc[sc];          // {ci0, nchunks, didx, 0}
    int b = blockIdx.y;

    __shared__ __align__(16) uint xs[XPAIR];
    __shared__ float sredm[4][CHUNK];
    __shared__ int   sredc[4][CHUNK];

    // copy this (batch, dilation) pair image once for all chunks (912 uint4)
    {
        const uint4* src = (const uint4*)(g_xpair + (b * NDIL + s.z) * XPAIR);
        uint4* dst = (uint4*)xs;
        #pragma unroll
        for (int i = 0; i < 8; i++) {
            int p = threadIdx.x + 128 * i;
            if (p < XPAIR / 4) dst[p] = src[p];
        }
    }
    __syncthreads();

    #pragma unroll 1
    for (int u = 0; u < s.y; u++) {
        if (u) __syncthreads();   // sred reuse barrier between chunks
        int ci = s.x + u;
        int4 ch = g_chunks[ci];
        if (ch.z == 7)      run_mma<7, 2>(ch, b, ci, xs, sredm, sredc, out);
        else if (ch.z == 9) run_mma<9, 2>(ch, b, ci, xs, sredm, sredc, out);
        else                run_mma<11, 3>(ch, b, ci, xs, sredm, sredc, out);
    }
}

// ---------------------------------------------------------------------------
// Launch
// ---------------------------------------------------------------------------
extern "C" void kernel_launch(void* const* d_in, const int* in_sizes, int n_in,
                              void* d_out, int out_size) {
    const float* x       = (const float*)d_in[0];
    const float* weights = (const float*)d_in[1];
    const float* biases  = (const float*)d_in[2];
    float* out = (float*)d_out;

    xpair_kernel<<<dim3(NDIL, BATCH), 256>>>(x);   // RNG-independent
    rng_par<<<(N_KERNELS + 255) / 256, 256>>>();
    group_fused<<<1, 1024>>>();
    wimg_kernel<<<MAXCH, 128>>>(weights, biases);

    rocket_mma<<<dim3(MAXSC, BATCH), 128>>>(out);
}

// round 13
// speedup vs baseline: 1.2563x; 1.2563x over previous
#include <cuda_runtime.h>
#include <cuda_fp16.h>
#include <stdint.h>

typedef unsigned long long ull;
typedef unsigned int uint;

// ---------------------------------------------------------------------------
// Problem constants
// ---------------------------------------------------------------------------
#define N_KERNELS 10000
#define IN_CH 3
#define T_LEN 1024
#define BATCH 64
#define MAXK 11
#define W_STRIDE (IN_CH * MAXK)     // 33
#define NGROUPS 15
#define NDIL 5
#define CHUNK 32                    // kernels per chunk (2 m-tiles of 16)
#define MAXCH 352
#define OUT_STRIDE (2 * N_KERNELS)
#define PADL 80
#define XPE 1216                    // PADL + 1024 + 96 (max right reach) + pad
#define XPAIR (IN_CH * XPE)         // 3648 u32 per (batch, dil)
#define NKMAX 3                     // k16 chunks: k=7:2, k=9:2, k=11:3

__constant__ int c_dils[NDIL] = {1, 2, 4, 8, 16};

// ---------------------------------------------------------------------------
// Device-global scratch
// ---------------------------------------------------------------------------
__device__ uint8_t g_kidx[N_KERNELS];
__device__ uint8_t g_didx[N_KERNELS];
__device__ uint8_t g_garr[N_KERNELS];
__device__ int     g_sorted[N_KERNELS];
__device__ int     g_nch;
__device__ int4    g_chunks[MAXCH];          // {start, count, k, didx}
__device__ int     g_rng_bad;                // static-init 0
__device__ __align__(16) uint4 g_wfrag[MAXCH * 2 * NKMAX * 32]; // A fragments
__device__ float   g_biasT[MAXCH * CHUNK];
__device__ __align__(16) uint g_xpair[BATCH * NDIL * XPAIR];    // {xh[i],xh[i+d]}

// ---------------------------------------------------------------------------
// NumPy default_rng(0): SeedSequence -> PCG64 (XSL-RR) -> Lemire  (validated)
// ---------------------------------------------------------------------------
#define PCG_MH 2549297995355413924ull
#define PCG_ML 4865540595714422341ull

struct Pcg { ull shi, slo, ihi, ilo; int has32; uint buf; };

__device__ __forceinline__ void mul128(ull alo, ull ahi, ull blo, ull bhi,
                                       ull &rlo, ull &rhi) {
    rlo = alo * blo;
    rhi = __umul64hi(alo, blo) + alo * bhi + ahi * blo;
}
__device__ __forceinline__ void add128(ull &alo, ull &ahi, ull blo, ull bhi) {
    ull t = alo + blo;
    ahi = ahi + bhi + (t < alo ? 1ull : 0ull);
    alo = t;
}
__device__ __forceinline__ void pcg_step(Pcg &p) {
    ull nlo, nhi;
    mul128(p.slo, p.shi, PCG_ML, PCG_MH, nlo, nhi);
    add128(nlo, nhi, p.ilo, p.ihi);
    p.slo = nlo; p.shi = nhi;
}
__device__ __forceinline__ ull pcg_out(ull slo, ull shi) {
    uint rot = (uint)(shi >> 58);
    ull x = shi ^ slo;
    return (x >> rot) | (x << ((64u - rot) & 63u));
}
__device__ __forceinline__ uint pcg_next32(Pcg &p) {
    if (p.has32) { p.has32 = 0; return p.buf; }
    pcg_step(p);
    ull v = pcg_out(p.slo, p.shi);
    p.has32 = 1;
    p.buf = (uint)(v >> 32);
    return (uint)v;
}
__device__ __forceinline__ uint lemire32(Pcg &p, uint excl) {
    ull m = (ull)pcg_next32(p) * (ull)excl;
    uint leftover = (uint)m;
    if (leftover < excl) {
        uint thr = (uint)(0u - excl) % excl;
        while (leftover < thr) {
            m = (ull)pcg_next32(p) * (ull)excl;
            leftover = (uint)m;
        }
    }
    return (uint)(m >> 32);
}
__device__ __forceinline__ uint hashmix32(uint v, uint *hc) {
    v ^= *hc; *hc *= 0x931e8875u; v *= *hc; v ^= v >> 16; return v;
}
__device__ __forceinline__ uint mix32(uint x, uint y) {
    uint r = x * 0xca01f9ddu - y * 0x4973f715u;
    r ^= r >> 16; return r;
}
__device__ void pcg_seed0(Pcg &p) {
    uint pool[4];
    uint hc = 0x43b0d7e5u;
    for (int i = 0; i < 4; i++) pool[i] = hashmix32(0u, &hc);
    for (int s = 0; s < 4; s++)
        for (int d = 0; d < 4; d++)
            if (s != d) pool[d] = mix32(pool[d], hashmix32(pool[s], &hc));
    uint hb = 0x8b51f9ddu;
    uint w32[8];
    for (int i = 0; i < 8; i++) {
        uint v = pool[i & 3];
        v ^= hb; hb *= 0x58f38dedu; v *= hb; v ^= v >> 16;
        w32[i] = v;
    }
    ull s0 = (ull)w32[0] | ((ull)w32[1] << 32);
    ull s1 = (ull)w32[2] | ((ull)w32[3] << 32);
    ull s2 = (ull)w32[4] | ((ull)w32[5] << 32);
    ull s3 = (ull)w32[6] | ((ull)w32[7] << 32);
    p.shi = 0; p.slo = 0;
    p.ihi = (s2 << 1) | (s3 >> 63);
    p.ilo = (s3 << 1) | 1ull;
    p.has32 = 0; p.buf = 0;
    pcg_step(p);
    add128(p.slo, p.shi, s1, s0);
    pcg_step(p);
}

// Parallel RNG via LCG jump-ahead; flags the (p~5e-6) Lemire-rejection case.
__global__ void rng_par() {
    int n = blockIdx.x * blockDim.x + threadIdx.x;
    if (n >= N_KERNELS) return;
    Pcg p;
    pcg_seed0(p);
    ull delta = (ull)(n + 1);
    ull am_lo = 1, am_hi = 0, ap_lo = 0, ap_hi = 0;
    ull cm_lo = PCG_ML, cm_hi = PCG_MH;
    ull cp_lo = p.ilo, cp_hi = p.ihi;
    while (delta) {
        if (delta & 1) {
            ull tlo, thi;
            mul128(am_lo, am_hi, cm_lo, cm_hi, tlo, thi);
            am_lo = tlo; am_hi = thi;
            mul128(ap_lo, ap_hi, cm_lo, cm_hi, tlo, thi);
            add128(tlo, thi, cp_lo, cp_hi);
            ap_lo = tlo; ap_hi = thi;
        }
        ull e_lo = cm_lo + 1;
        ull e_hi = cm_hi + (e_lo == 0 ? 1ull : 0ull);
        ull tlo, thi;
        mul128(e_lo, e_hi, cp_lo, cp_hi, tlo, thi);
        cp_lo = tlo; cp_hi = thi;
        mul128(cm_lo, cm_hi, cm_lo, cm_hi, tlo, thi);
        cm_lo = tlo; cm_hi = thi;
        delta >>= 1;
    }
    ull slo, shi;
    mul128(p.slo, p.shi, am_lo, am_hi, slo, shi);
    add128(slo, shi, ap_lo, ap_hi);
    ull out = pcg_out(slo, shi);
    uint lo = (uint)out;
    uint hi = (uint)(out >> 32);
    if (lo == 0u || hi == 0u) atomicOr(&g_rng_bad, 1);
    if (n < N_KERNELS / 2) {
        int j = 2 * n;
        g_kidx[j]     = (uint8_t)(((ull)lo * 3ull) >> 32);
        g_kidx[j + 1] = (uint8_t)(((ull)hi * 3ull) >> 32);
    } else {
        int j = 2 * n - N_KERNELS;
        g_didx[j]     = (uint8_t)(((ull)lo * 5ull) >> 32);
        g_didx[j + 1] = (uint8_t)(((ull)hi * 5ull) >> 32);
    }
}

// ---------------------------------------------------------------------------
// Fused: sequential RNG fallback (rare) + grouping + chunk table.
// Dilation-major group id (g = didx*3 + kidx).
// ---------------------------------------------------------------------------
__global__ void __launch_bounds__(1024)
group_fused() {
    __shared__ int cnt[NGROUPS];
    __shared__ int off[NGROUPS];
    int tid = threadIdx.x;

    if (tid == 0 && g_rng_bad) {       // exact sequential fallback
        Pcg p;
        pcg_seed0(p);
        for (int i = 0; i < N_KERNELS; i++) g_kidx[i] = (uint8_t)lemire32(p, 3u);
        for (int i = 0; i < N_KERNELS; i++) g_didx[i] = (uint8_t)lemire32(p, 5u);
        g_rng_bad = 0;
    }
    if (tid < NGROUPS) cnt[tid] = 0;
    __syncthreads();

    for (int i = tid; i < N_KERNELS; i += 1024) {
        int g = (int)g_didx[i] * 3 + (int)g_kidx[i];
        g_garr[i] = (uint8_t)g;
        atomicAdd(&cnt[g], 1);
    }
    __syncthreads();

    if (tid == 0) {
        int o = 0, nch = 0;
        for (int g = 0; g < NGROUPS; g++) {
            int ks   = 7 + 2 * (g % 3);
            int didx = g / 3;
            int n    = cnt[g];
            off[g] = o;
            for (int s = 0; s < n; s += CHUNK) {
                int4 ch;
                ch.x = o + s;
                ch.y = (n - s < CHUNK) ? (n - s) : CHUNK;
                ch.z = ks;
                ch.w = didx;
                g_chunks[nch++] = ch;
            }
            o += n;
        }
        g_nch = nch;
    }
    __syncthreads();

    for (int i = tid; i < N_KERNELS; i += 1024) {
        int p = atomicAdd(&off[g_garr[i]], 1);
        g_sorted[p] = i;
    }
}

// ---------------------------------------------------------------------------
// A-fragment image: fp16 weights, tap-pair K layout.
// Per channel c: S = k+1 slots (even); slot j<k holds w[c][j], slot k = 0.
// ---------------------------------------------------------------------------
__device__ __forceinline__ unsigned short whalf(const float* __restrict__ weights,
                                                const int* __restrict__ sorted,
                                                int start, int count, int k,
                                                int row, int slot) {
    int S = k + 1;
    float v = 0.0f;
    if (row < count && slot < 3 * S) {
        int c = slot / S;
        int j = slot - c * S;
        if (j < k)
            v = weights[sorted[start + row] * W_STRIDE + c * MAXK + j];
    }
    __half h = __float2half(v);
    unsigned short u;
    memcpy(&u, &h, 2);
    return u;
}

__global__ void wimg_kernel(const float* __restrict__ weights,
                            const float* __restrict__ biases) {
    int ci = blockIdx.x;
    if (ci >= g_nch) return;
    int4 ch = g_chunks[ci];
    int start = ch.x, count = ch.y, k = ch.z;

    for (int idx = threadIdx.x; idx < 2 * NKMAX * 32; idx += blockDim.x) {
        int mt   = idx / (NKMAX * 32);
        int rem  = idx - mt * (NKMAX * 32);
        int kc   = rem / 32;
        int lane = rem & 31;
        int g = lane >> 2;
        int t = lane & 3;
        int r0 = mt * 16 + g;
        int r1 = r0 + 8;
        int k0 = kc * 16 + 2 * t;
        uint4 f;
        f.x = (uint)whalf(weights, g_sorted, start, count, k, r0, k0)
            | ((uint)whalf(weights, g_sorted, start, count, k, r0, k0 + 1) << 16);
        f.y = (uint)whalf(weights, g_sorted, start, count, k, r1, k0)
            | ((uint)whalf(weights, g_sorted, start, count, k, r1, k0 + 1) << 16);
        f.z = (uint)whalf(weights, g_sorted, start, count, k, r0, k0 + 8)
            | ((uint)whalf(weights, g_sorted, start, count, k, r0, k0 + 9) << 16);
        f.w = (uint)whalf(weights, g_sorted, start, count, k, r1, k0 + 8)
            | ((uint)whalf(weights, g_sorted, start, count, k, r1, k0 + 9) << 16);
        g_wfrag[(ci * 2 + mt) * (NKMAX * 32) + kc * 32 + lane] = f;
    }
    if (threadIdx.x < CHUNK) {
        float b = 0.0f;
        if (threadIdx.x < count) b = biases[g_sorted[start + threadIdx.x]];
        g_biasT[ci * CHUNK + threadIdx.x] = b;
    }
}

// ---------------------------------------------------------------------------
// Pair image per (batch, dilation): P[c][i] = {fp16(x[i-PADL]), fp16(x[i-PADL+d])}
// ---------------------------------------------------------------------------
__global__ void xpair_kernel(const float* __restrict__ x) {
    int d_idx = blockIdx.x;
    int b = blockIdx.y;
    int dil = c_dils[d_idx];
    uint* dst = g_xpair + (b * NDIL + d_idx) * XPAIR;
    const float* xb = x + b * IN_CH * T_LEN;
    for (int i = threadIdx.x; i < XPAIR; i += blockDim.x) {
        int c = i / XPE;
        int p = i - c * XPE;
        int t1 = p - PADL;
        int t2 = t1 + dil;
        float f1 = ((unsigned)t1 < T_LEN) ? xb[c * T_LEN + t1] : 0.0f;
        float f2 = ((unsigned)t2 < T_LEN) ? xb[c * T_LEN + t2] : 0.0f;
        __half h1 = __float2half(f1);
        __half h2 = __float2half(f2);
        unsigned short u1, u2;
        memcpy(&u1, &h1, 2);
        memcpy(&u2, &h2, 2);
        dst[i] = (uint)u1 | ((uint)u2 << 16);
    }
}

// ---------------------------------------------------------------------------
// Main HMMA kernel: ONE chunk per block (uniform blocks, max parallelism)
// ---------------------------------------------------------------------------
__device__ __forceinline__ void mma16816h(float c[4], uint4 a, uint b0, uint b1) {
    asm("mma.sync.aligned.m16n8k16.row.col.f32.f16.f16.f32 "
        "{%0,%1,%2,%3}, {%4,%5,%6,%7}, {%8,%9}, {%0,%1,%2,%3};"
        : "+f"(c[0]), "+f"(c[1]), "+f"(c[2]), "+f"(c[3])
        : "r"(a.x), "r"(a.y), "r"(a.z), "r"(a.w), "r"(b0), "r"(b1));
}

// Base u32 index into the pair image for EVEN K slot s (pair base tap).
template <int K>
__device__ __forceinline__ int pslot(int s, int dil) {
    const int S = K + 1;
    const int h = (K - 1) / 2;
    if (s >= 3 * S) return 0;
    int c = s / S;
    int j = s - c * S;
    return c * XPE + PADL + (j - h) * dil;
}

template <int K, int NK>
__device__ __forceinline__ void run_mma(int4 ch, int b, int ci,
                                        const uint* __restrict__ xs,
                                        float (*sredm)[CHUNK], int (*sredc)[CHUNK],
                                        float* __restrict__ out) {
    const int tid  = threadIdx.x;
    const int warp = tid >> 5;
    const int lane = tid & 31;
    const int g = lane >> 2;
    const int t = lane & 3;
    const int dil = 1 << ch.w;
    const int wg = warp * 256 + g;

    // B base indices (u32) per kc for this lane
    uint ix0[NK], ix1[NK];
    #pragma unroll
    for (int kc = 0; kc < NK; kc++) {
        ix0[kc] = (uint)(pslot<K>(kc * 16 + 2 * t, dil) + wg);
        ix1[kc] = (uint)(pslot<K>(kc * 16 + 2 * t + 8, dil) + wg);
    }

    // A fragments (registers for the whole block)
    uint4 a0[NK], a1[NK];
    {
        const uint4* wf = g_wfrag + (ci * 2) * (NKMAX * 32);
        #pragma unroll
        for (int kc = 0; kc < NK; kc++) {
            a0[kc] = wf[kc * 32 + lane];
            a1[kc] = wf[NKMAX * 32 + kc * 32 + lane];
        }
    }

    // negated biases for this thread's 4 C rows
    float nb[4];
    nb[0] = -g_biasT[ci * CHUNK + g];
    nb[1] = -g_biasT[ci * CHUNK + g + 8];
    nb[2] = -g_biasT[ci * CHUNK + 16 + g];
    nb[3] = -g_biasT[ci * CHUNK + 24 + g];

    float mx[4] = {-3.4e38f, -3.4e38f, -3.4e38f, -3.4e38f};
    int ct[4] = {0, 0, 0, 0};

    #pragma unroll 8
    for (int nt = 0; nt < 32; nt++) {
        float C0[4] = {0, 0, 0, 0};
        float C1[4] = {0, 0, 0, 0};
        #pragma unroll
        for (int kc = 0; kc < NK; kc++) {
            uint b0 = xs[ix0[kc] + nt * 8];
            uint b1 = xs[ix1[kc] + nt * 8];
            mma16816h(C0, a0[kc], b0, b1);
            mma16816h(C1, a1[kc], b0, b1);
        }
        mx[0] = fmaxf(mx[0], fmaxf(C0[0], C0[1]));
        mx[1] = fmaxf(mx[1], fmaxf(C0[2], C0[3]));
        mx[2] = fmaxf(mx[2], fmaxf(C1[0], C1[1]));
        mx[3] = fmaxf(mx[3], fmaxf(C1[2], C1[3]));
        if (C0[0] > nb[0]) ct[0]++;
        if (C0[1] > nb[0]) ct[0]++;
        if (C0[2] > nb[1]) ct[1]++;
        if (C0[3] > nb[1]) ct[1]++;
        if (C1[0] > nb[2]) ct[2]++;
        if (C1[1] > nb[2]) ct[2]++;
        if (C1[2] > nb[3]) ct[3]++;
        if (C1[3] > nb[3]) ct[3]++;
    }

    // reduce across the 4 threads sharing each row
    #pragma unroll
    for (int o = 1; o <= 2; o <<= 1) {
        #pragma unroll
        for (int i = 0; i < 4; i++) {
            mx[i] = fmaxf(mx[i], __shfl_xor_sync(0xffffffffu, mx[i], o));
            ct[i] += __shfl_xor_sync(0xffffffffu, ct[i], o);
        }
    }
    if (t == 0) {
        sredm[warp][g]      = mx[0];  sredc[warp][g]      = ct[0];
        sredm[warp][g + 8]  = mx[1];  sredc[warp][g + 8]  = ct[1];
        sredm[warp][g + 16] = mx[2];  sredc[warp][g + 16] = ct[2];
        sredm[warp][g + 24] = mx[3];  sredc[warp][g + 24] = ct[3];
    }
    __syncthreads();

    if (tid < CHUNK && tid < ch.y) {
        float m = sredm[0][tid];
        int c2 = sredc[0][tid];
        #pragma unroll
        for (int w = 1; w < 4; w++) {
            m = fmaxf(m, sredm[w][tid]);
            c2 += sredc[w][tid];
        }
        int orig = g_sorted[ch.x + tid];
        float bias = g_biasT[ci * CHUNK + tid];
        float2 o;
        o.x = m + bias;
        o.y = (float)c2 * (1.0f / 1024.0f);
        *(float2*)(out + (size_t)b * OUT_STRIDE + 2 * orig) = o;
    }
}

__global__ void __launch_bounds__(128)
rocket_mma(float* __restrict__ out) {
    int ci = blockIdx.x;
    if (ci >= g_nch) return;
    int4 ch = g_chunks[ci];
    int b = blockIdx.y;

    __shared__ __align__(16) uint xs[XPAIR];
    __shared__ float sredm[4][CHUNK];
    __shared__ int   sredc[4][CHUNK];

    // copy this (batch, dilation) pair image (912 uint4)
    {
        const uint4* src = (const uint4*)(g_xpair + (b * NDIL + ch.w) * XPAIR);
        uint4* dst = (uint4*)xs;
        #pragma unroll
        for (int i = 0; i < 8; i++) {
            int p = threadIdx.x + 128 * i;
            if (p < XPAIR / 4) dst[p] = src[p];
        }
    }
    __syncthreads();

    if (ch.z == 7)      run_mma<7, 2>(ch, b, ci, xs, sredm, sredc, out);
    else if (ch.z == 9) run_mma<9, 2>(ch, b, ci, xs, sredm, sredc, out);
    else                run_mma<11, 3>(ch, b, ci, xs, sredm, sredc, out);
}

// ---------------------------------------------------------------------------
// Launch
// ---------------------------------------------------------------------------
extern "C" void kernel_launch(void* const* d_in, const int* in_sizes, int n_in,
                              void* d_out, int out_size) {
    const float* x       = (const float*)d_in[0];
    const float* weights = (const float*)d_in[1];
    const float* biases  = (const float*)d_in[2];
    float* out = (float*)d_out;

    xpair_kernel<<<dim3(NDIL, BATCH), 256>>>(x);   // RNG-independent
    rng_par<<<(N_KERNELS + 255) / 256, 256>>>();
    group_fused<<<1, 1024>>>();
    wimg_kernel<<<MAXCH, 128>>>(weights, biases);

    rocket_mma<<<dim3(MAXCH, BATCH), 128>>>(out);
}

// round 14
// speedup vs baseline: 1.3462x; 1.0715x over previous
#include <cuda_runtime.h>
#include <cuda_fp16.h>
#include <stdint.h>

typedef unsigned long long ull;
typedef unsigned int uint;

// ---------------------------------------------------------------------------
// Problem constants
// ---------------------------------------------------------------------------
#define N_KERNELS 10000
#define IN_CH 3
#define T_LEN 1024
#define BATCH 64
#define MAXK 11
#define W_STRIDE (IN_CH * MAXK)     // 33
#define NGROUPS 15
#define NDIL 5
#define CHUNK 32                    // kernels per chunk (2 m-tiles of 16)
#define MAXCH 352
#define OUT_STRIDE (2 * N_KERNELS)
#define PADL 80
#define XPE 1216                    // PADL + 1024 + 96 (max right reach) + pad
#define XPAIR (IN_CH * XPE)         // 3648 u32 per (batch, dil)
#define NKMAX 3                     // k16 chunks: k=7:2, k=9:2, k=11:3

__constant__ int c_dils[NDIL] = {1, 2, 4, 8, 16};

// ---------------------------------------------------------------------------
// Device-global scratch
// ---------------------------------------------------------------------------
__device__ uint8_t g_kidx[N_KERNELS];
__device__ uint8_t g_didx[N_KERNELS];
__device__ uint8_t g_garr[N_KERNELS];
__device__ int     g_sorted[N_KERNELS];
__device__ int     g_nch;
__device__ int4    g_chunks[MAXCH];          // {start, count, k, didx}
__device__ int     g_rng_bad;                // static-init 0
__device__ __align__(16) uint4 g_wfrag[MAXCH * 2 * NKMAX * 32]; // A fragments
__device__ float   g_biasT[MAXCH * CHUNK];
__device__ __align__(16) uint g_xpair[BATCH * NDIL * XPAIR];    // {xh[i],xh[i+d]}

// ---------------------------------------------------------------------------
// NumPy default_rng(0): SeedSequence -> PCG64 (XSL-RR) -> Lemire  (validated)
// ---------------------------------------------------------------------------
#define PCG_MH 2549297995355413924ull
#define PCG_ML 4865540595714422341ull

struct Pcg { ull shi, slo, ihi, ilo; int has32; uint buf; };

__device__ __forceinline__ void mul128(ull alo, ull ahi, ull blo, ull bhi,
                                       ull &rlo, ull &rhi) {
    rlo = alo * blo;
    rhi = __umul64hi(alo, blo) + alo * bhi + ahi * blo;
}
__device__ __forceinline__ void add128(ull &alo, ull &ahi, ull blo, ull bhi) {
    ull t = alo + blo;
    ahi = ahi + bhi + (t < alo ? 1ull : 0ull);
    alo = t;
}
__device__ __forceinline__ void pcg_step(Pcg &p) {
    ull nlo, nhi;
    mul128(p.slo, p.shi, PCG_ML, PCG_MH, nlo, nhi);
    add128(nlo, nhi, p.ilo, p.ihi);
    p.slo = nlo; p.shi = nhi;
}
__device__ __forceinline__ ull pcg_out(ull slo, ull shi) {
    uint rot = (uint)(shi >> 58);
    ull x = shi ^ slo;
    return (x >> rot) | (x << ((64u - rot) & 63u));
}
__device__ __forceinline__ uint pcg_next32(Pcg &p) {
    if (p.has32) { p.has32 = 0; return p.buf; }
    pcg_step(p);
    ull v = pcg_out(p.slo, p.shi);
    p.has32 = 1;
    p.buf = (uint)(v >> 32);
    return (uint)v;
}
__device__ __forceinline__ uint lemire32(Pcg &p, uint excl) {
    ull m = (ull)pcg_next32(p) * (ull)excl;
    uint leftover = (uint)m;
    if (leftover < excl) {
        uint thr = (uint)(0u - excl) % excl;
        while (leftover < thr) {
            m = (ull)pcg_next32(p) * (ull)excl;
            leftover = (uint)m;
        }
    }
    return (uint)(m >> 32);
}
__device__ __forceinline__ uint hashmix32(uint v, uint *hc) {
    v ^= *hc; *hc *= 0x931e8875u; v *= *hc; v ^= v >> 16; return v;
}
__device__ __forceinline__ uint mix32(uint x, uint y) {
    uint r = x * 0xca01f9ddu - y * 0x4973f715u;
    r ^= r >> 16; return r;
}
__device__ void pcg_seed0(Pcg &p) {
    uint pool[4];
    uint hc = 0x43b0d7e5u;
    for (int i = 0; i < 4; i++) pool[i] = hashmix32(0u, &hc);
    for (int s = 0; s < 4; s++)
        for (int d = 0; d < 4; d++)
            if (s != d) pool[d] = mix32(pool[d], hashmix32(pool[s], &hc));
    uint hb = 0x8b51f9ddu;
    uint w32[8];
    for (int i = 0; i < 8; i++) {
        uint v = pool[i & 3];
        v ^= hb; hb *= 0x58f38dedu; v *= hb; v ^= v >> 16;
        w32[i] = v;
    }
    ull s0 = (ull)w32[0] | ((ull)w32[1] << 32);
    ull s1 = (ull)w32[2] | ((ull)w32[3] << 32);
    ull s2 = (ull)w32[4] | ((ull)w32[5] << 32);
    ull s3 = (ull)w32[6] | ((ull)w32[7] << 32);
    p.shi = 0; p.slo = 0;
    p.ihi = (s2 << 1) | (s3 >> 63);
    p.ilo = (s3 << 1) | 1ull;
    p.has32 = 0; p.buf = 0;
    pcg_step(p);
    add128(p.slo, p.shi, s1, s0);
    pcg_step(p);
}

// Parallel RNG via LCG jump-ahead; flags the (p~5e-6) Lemire-rejection case.
__global__ void rng_par() {
    int n = blockIdx.x * blockDim.x + threadIdx.x;
    if (n >= N_KERNELS) return;
    Pcg p;
    pcg_seed0(p);
    ull delta = (ull)(n + 1);
    ull am_lo = 1, am_hi = 0, ap_lo = 0, ap_hi = 0;
    ull cm_lo = PCG_ML, cm_hi = PCG_MH;
    ull cp_lo = p.ilo, cp_hi = p.ihi;
    while (delta) {
        if (delta & 1) {
            ull tlo, thi;
            mul128(am_lo, am_hi, cm_lo, cm_hi, tlo, thi);
            am_lo = tlo; am_hi = thi;
            mul128(ap_lo, ap_hi, cm_lo, cm_hi, tlo, thi);
            add128(tlo, thi, cp_lo, cp_hi);
            ap_lo = tlo; ap_hi = thi;
        }
        ull e_lo = cm_lo + 1;
        ull e_hi = cm_hi + (e_lo == 0 ? 1ull : 0ull);
        ull tlo, thi;
        mul128(e_lo, e_hi, cp_lo, cp_hi, tlo, thi);
        cp_lo = tlo; cp_hi = thi;
        mul128(cm_lo, cm_hi, cm_lo, cm_hi, tlo, thi);
        cm_lo = tlo; cm_hi = thi;
        delta >>= 1;
    }
    ull slo, shi;
    mul128(p.slo, p.shi, am_lo, am_hi, slo, shi);
    add128(slo, shi, ap_lo, ap_hi);
    ull out = pcg_out(slo, shi);
    uint lo = (uint)out;
    uint hi = (uint)(out >> 32);
    if (lo == 0u || hi == 0u) atomicOr(&g_rng_bad, 1);
    if (n < N_KERNELS / 2) {
        int j = 2 * n;
        g_kidx[j]     = (uint8_t)(((ull)lo * 3ull) >> 32);
        g_kidx[j + 1] = (uint8_t)(((ull)hi * 3ull) >> 32);
    } else {
        int j = 2 * n - N_KERNELS;
        g_didx[j]     = (uint8_t)(((ull)lo * 5ull) >> 32);
        g_didx[j + 1] = (uint8_t)(((ull)hi * 5ull) >> 32);
    }
}

// ---------------------------------------------------------------------------
// Fused: sequential RNG fallback (rare) + grouping + chunk table.
// Dilation-major group id (g = didx*3 + kidx).
// ---------------------------------------------------------------------------
__global__ void __launch_bounds__(1024)
group_fused() {
    __shared__ int cnt[NGROUPS];
    __shared__ int off[NGROUPS];
    int tid = threadIdx.x;

    if (tid == 0 && g_rng_bad) {       // exact sequential fallback
        Pcg p;
        pcg_seed0(p);
        for (int i = 0; i < N_KERNELS; i++) g_kidx[i] = (uint8_t)lemire32(p, 3u);
        for (int i = 0; i < N_KERNELS; i++) g_didx[i] = (uint8_t)lemire32(p, 5u);
        g_rng_bad = 0;
    }
    if (tid < NGROUPS) cnt[tid] = 0;
    __syncthreads();

    for (int i = tid; i < N_KERNELS; i += 1024) {
        int g = (int)g_didx[i] * 3 + (int)g_kidx[i];
        g_garr[i] = (uint8_t)g;
        atomicAdd(&cnt[g], 1);
    }
    __syncthreads();

    if (tid == 0) {
        int o = 0, nch = 0;
        for (int g = 0; g < NGROUPS; g++) {
            int ks   = 7 + 2 * (g % 3);
            int didx = g / 3;
            int n    = cnt[g];
            off[g] = o;
            for (int s = 0; s < n; s += CHUNK) {
                int4 ch;
                ch.x = o + s;
                ch.y = (n - s < CHUNK) ? (n - s) : CHUNK;
                ch.z = ks;
                ch.w = didx;
                g_chunks[nch++] = ch;
            }
            o += n;
        }
        g_nch = nch;
    }
    __syncthreads();

    for (int i = tid; i < N_KERNELS; i += 1024) {
        int p = atomicAdd(&off[g_garr[i]], 1);
        g_sorted[p] = i;
    }
}

// ---------------------------------------------------------------------------
// A-fragment image: fp16 weights, tap-pair K layout (templated on K so the
// slot->(c,j) divides are compile-time).
// Per channel c: S = k+1 slots (even); slot j<k holds w[c][j], slot k = 0.
// ---------------------------------------------------------------------------
template <int K>
__device__ __forceinline__ unsigned short whalf(const float* __restrict__ weights,
                                                const int* __restrict__ sorted,
                                                int start, int count,
                                                int row, int slot) {
    const int S = K + 1;
    float v = 0.0f;
    if (row < count && slot < 3 * S) {
        int c = slot / S;
        int j = slot - c * S;
        if (j < K)
            v = weights[sorted[start + row] * W_STRIDE + c * MAXK + j];
    }
    __half h = __float2half(v);
    unsigned short u;
    memcpy(&u, &h, 2);
    return u;
}

template <int K>
__device__ __forceinline__ void wimg_body(const float* __restrict__ weights,
                                          int ci, int start, int count) {
    for (int idx = threadIdx.x; idx < 2 * NKMAX * 32; idx += blockDim.x) {
        int mt   = idx / (NKMAX * 32);
        int rem  = idx - mt * (NKMAX * 32);
        int kc   = rem / 32;
        int lane = rem & 31;
        int g = lane >> 2;
        int t = lane & 3;
        int r0 = mt * 16 + g;
        int r1 = r0 + 8;
        int k0 = kc * 16 + 2 * t;
        uint4 f;
        f.x = (uint)whalf<K>(weights, g_sorted, start, count, r0, k0)
            | ((uint)whalf<K>(weights, g_sorted, start, count, r0, k0 + 1) << 16);
        f.y = (uint)whalf<K>(weights, g_sorted, start, count, r1, k0)
            | ((uint)whalf<K>(weights, g_sorted, start, count, r1, k0 + 1) << 16);
        f.z = (uint)whalf<K>(weights, g_sorted, start, count, r0, k0 + 8)
            | ((uint)whalf<K>(weights, g_sorted, start, count, r0, k0 + 9) << 16);
        f.w = (uint)whalf<K>(weights, g_sorted, start, count, r1, k0 + 8)
            | ((uint)whalf<K>(weights, g_sorted, start, count, r1, k0 + 9) << 16);
        g_wfrag[(ci * 2 + mt) * (NKMAX * 32) + kc * 32 + lane] = f;
    }
}

__global__ void wimg_kernel(const float* __restrict__ weights,
                            const float* __restrict__ biases) {
    int ci = blockIdx.x;
    if (ci >= g_nch) return;
    int4 ch = g_chunks[ci];
    int start = ch.x, count = ch.y;

    if (ch.z == 7)      wimg_body<7>(weights, ci, start, count);
    else if (ch.z == 9) wimg_body<9>(weights, ci, start, count);
    else                wimg_body<11>(weights, ci, start, count);

    if (threadIdx.x < CHUNK) {
        float b = 0.0f;
        if (threadIdx.x < count) b = biases[g_sorted[start + threadIdx.x]];
        g_biasT[ci * CHUNK + threadIdx.x] = b;
    }
}

// ---------------------------------------------------------------------------
// Pair image per (batch, dilation): P[c][i] = {fp16(x[i-PADL]), fp16(x[i-PADL+d])}
// ---------------------------------------------------------------------------
__global__ void xpair_kernel(const float* __restrict__ x) {
    int d_idx = blockIdx.x;
    int b = blockIdx.y;
    int dil = c_dils[d_idx];
    uint* dst = g_xpair + (b * NDIL + d_idx) * XPAIR;
    const float* xb = x + b * IN_CH * T_LEN;
    for (int i = threadIdx.x; i < XPAIR; i += blockDim.x) {
        int c = i / XPE;
        int p = i - c * XPE;
        int t1 = p - PADL;
        int t2 = t1 + dil;
        float f1 = ((unsigned)t1 < T_LEN) ? xb[c * T_LEN + t1] : 0.0f;
        float f2 = ((unsigned)t2 < T_LEN) ? xb[c * T_LEN + t2] : 0.0f;
        __half h1 = __float2half(f1);
        __half h2 = __float2half(f2);
        unsigned short u1, u2;
        memcpy(&u1, &h1, 2);
        memcpy(&u2, &h2, 2);
        dst[i] = (uint)u1 | ((uint)u2 << 16);
    }
}

// ---------------------------------------------------------------------------
// Main HMMA kernel: one chunk per block; f16x2-packed epilogue.
// C fragment pairs (c0,c1)/(c2,c3) are same-row adjacent columns -> packed
// half2 max + threshold-count with per-row packed thresholds.
// ---------------------------------------------------------------------------
__device__ __forceinline__ void mma16816h(float c[4], uint4 a, uint b0, uint b1) {
    asm("mma.sync.aligned.m16n8k16.row.col.f32.f16.f16.f32 "
        "{%0,%1,%2,%3}, {%4,%5,%6,%7}, {%8,%9}, {%0,%1,%2,%3};"
        : "+f"(c[0]), "+f"(c[1]), "+f"(c[2]), "+f"(c[3])
        : "r"(a.x), "r"(a.y), "r"(a.z), "r"(a.w), "r"(b0), "r"(b1));
}

// Base u32 index into the pair image for EVEN K slot s (pair base tap).
template <int K>
__device__ __forceinline__ int pslot(int s, int dil) {
    const int S = K + 1;
    const int h = (K - 1) / 2;
    if (s >= 3 * S) return 0;
    int c = s / S;
    int j = s - c * S;
    return c * XPE + PADL + (j - h) * dil;
}

template <int K, int NK>
__device__ __forceinline__ void run_mma(int4 ch, int b, int ci,
                                        const uint* __restrict__ xs,
                                        float (*sredm)[CHUNK], float (*sredc)[CHUNK],
                                        float* __restrict__ out) {
    const int tid  = threadIdx.x;
    const int warp = tid >> 5;
    const int lane = tid & 31;
    const int g = lane >> 2;
    const int t = lane & 3;
    const int dil = 1 << ch.w;
    const int wg = warp * 256 + g;

    // B base indices (u32) per kc for this lane
    uint ix0[NK], ix1[NK];
    #pragma unroll
    for (int kc = 0; kc < NK; kc++) {
        ix0[kc] = (uint)(pslot<K>(kc * 16 + 2 * t, dil) + wg);
        ix1[kc] = (uint)(pslot<K>(kc * 16 + 2 * t + 8, dil) + wg);
    }

    // A fragments (registers for the whole block)
    uint4 a0[NK], a1[NK];
    {
        const uint4* wf = g_wfrag + (ci * 2) * (NKMAX * 32);
        #pragma unroll
        for (int kc = 0; kc < NK; kc++) {
            a0[kc] = wf[kc * 32 + lane];
            a1[kc] = wf[NKMAX * 32 + kc * 32 + lane];
        }
    }

    // packed per-row thresholds {-bias, -bias} for this thread's 4 C rows
    __half2 nbh[4];
    nbh[0] = __float2half2_rn(-g_biasT[ci * CHUNK + g]);
    nbh[1] = __float2half2_rn(-g_biasT[ci * CHUNK + g + 8]);
    nbh[2] = __float2half2_rn(-g_biasT[ci * CHUNK + 16 + g]);
    nbh[3] = __float2half2_rn(-g_biasT[ci * CHUNK + 24 + g]);

    __half2 pmx[4], pct[4];
    #pragma unroll
    for (int i = 0; i < 4; i++) {
        pmx[i] = __float2half2_rn(-60000.0f);
        pct[i] = __float2half2_rn(0.0f);
    }

    #pragma unroll 8
    for (int nt = 0; nt < 32; nt++) {
        float C0[4] = {0, 0, 0, 0};
        float C1[4] = {0, 0, 0, 0};
        #pragma unroll
        for (int kc = 0; kc < NK; kc++) {
            uint b0 = xs[ix0[kc] + nt * 8];
            uint b1 = xs[ix1[kc] + nt * 8];
            mma16816h(C0, a0[kc], b0, b1);
            mma16816h(C1, a1[kc], b0, b1);
        }
        {
            __half2 p0 = __floats2half2_rn(C0[0], C0[1]);
            __half2 p1 = __floats2half2_rn(C0[2], C0[3]);
            __half2 p2 = __floats2half2_rn(C1[0], C1[1]);
            __half2 p3 = __floats2half2_rn(C1[2], C1[3]);
            pmx[0] = __hmax2(pmx[0], p0);
            pmx[1] = __hmax2(pmx[1], p1);
            pmx[2] = __hmax2(pmx[2], p2);
            pmx[3] = __hmax2(pmx[3], p3);
            pct[0] = __hadd2(pct[0], __hgt2(p0, nbh[0]));
            pct[1] = __hadd2(pct[1], __hgt2(p1, nbh[1]));
            pct[2] = __hadd2(pct[2], __hgt2(p2, nbh[2]));
            pct[3] = __hadd2(pct[3], __hgt2(p3, nbh[3]));
        }
    }

    // unpack lanes, reduce across the 4 threads sharing each row
    float mx[4], ct[4];
    #pragma unroll
    for (int i = 0; i < 4; i++) {
        float2 mf = __half22float2(pmx[i]);
        mx[i] = fmaxf(mf.x, mf.y);
        float2 cf = __half22float2(pct[i]);
        ct[i] = cf.x + cf.y;
    }
    #pragma unroll
    for (int o = 1; o <= 2; o <<= 1) {
        #pragma unroll
        for (int i = 0; i < 4; i++) {
            mx[i] = fmaxf(mx[i], __shfl_xor_sync(0xffffffffu, mx[i], o));
            ct[i] += __shfl_xor_sync(0xffffffffu, ct[i], o);
        }
    }
    if (t == 0) {
        sredm[warp][g]      = mx[0];  sredc[warp][g]      = ct[0];
        sredm[warp][g + 8]  = mx[1];  sredc[warp][g + 8]  = ct[1];
        sredm[warp][g + 16] = mx[2];  sredc[warp][g + 16] = ct[2];
        sredm[warp][g + 24] = mx[3];  sredc[warp][g + 24] = ct[3];
    }
    __syncthreads();

    if (tid < CHUNK && tid < ch.y) {
        float m = sredm[0][tid];
        float c2 = sredc[0][tid];
        #pragma unroll
        for (int w = 1; w < 4; w++) {
            m = fmaxf(m, sredm[w][tid]);
            c2 += sredc[w][tid];
        }
        int orig = g_sorted[ch.x + tid];
        float bias = g_biasT[ci * CHUNK + tid];
        float2 o;
        o.x = m + bias;
        o.y = c2 * (1.0f / 1024.0f);
        *(float2*)(out + (size_t)b * OUT_STRIDE + 2 * orig) = o;
    }
}

__global__ void __launch_bounds__(128)
rocket_mma(float* __restrict__ out) {
    int ci = blockIdx.x;
    if (ci >= g_nch) return;
    int4 ch = g_chunks[ci];
    int b = blockIdx.y;

    __shared__ __align__(16) uint xs[XPAIR];
    __shared__ float sredm[4][CHUNK];
    __shared__ float sredc[4][CHUNK];

    // copy this (batch, dilation) pair image (912 uint4)
    {
        const uint4* src = (const uint4*)(g_xpair + (b * NDIL + ch.w) * XPAIR);
        uint4* dst = (uint4*)xs;
        #pragma unroll
        for (int i = 0; i < 8; i++) {
            int p = threadIdx.x + 128 * i;
            if (p < XPAIR / 4) dst[p] = src[p];
        }
    }
    __syncthreads();

    if (ch.z == 7)      run_mma<7, 2>(ch, b, ci, xs, sredm, sredc, out);
    else if (ch.z == 9) run_mma<9, 2>(ch, b, ci, xs, sredm, sredc, out);
    else                run_mma<11, 3>(ch, b, ci, xs, sredm, sredc, out);
}

// ---------------------------------------------------------------------------
// Launch
// ---------------------------------------------------------------------------
extern "C" void kernel_launch(void* const* d_in, const int* in_sizes, int n_in,
                              void* d_out, int out_size) {
    const float* x       = (const float*)d_in[0];
    const float* weights = (const float*)d_in[1];
    const float* biases  = (const float*)d_in[2];
    float* out = (float*)d_out;

    xpair_kernel<<<dim3(NDIL, BATCH), 256>>>(x);   // RNG-independent
    rng_par<<<(N_KERNELS + 255) / 256, 256>>>();
    group_fused<<<1, 1024>>>();
    wimg_kernel<<<MAXCH, 128>>>(weights, biases);

    rocket_mma<<<dim3(MAXCH, BATCH), 128>>>(out);
}